// round 12
// baseline (speedup 1.0000x reference)
#include <cuda_runtime.h>

#define NN 50000
#define NE 800000
#define D 128

// ---------------- device scratch (no allocations allowed) ----------------
__device__ int   d_is64;
__device__ int   d_deg[NN];
__device__ int   d_off[NN + 1];
__device__ int   d_cur[NN];
__device__ int   d_esrc[NE];
__device__ float d_agg[(size_t)NN * D];   // 25.6 MB mean-aggregated features

// ---------------- dtype detection: int64 vs int32 indices ----------------
// If indices are int64 (little-endian, values in [0,50000)), every odd 32-bit
// word is 0. If int32, odd words are random dst/src indices (P(all zero)≈0).
__global__ void detect_kernel(const int* __restrict__ src32,
                              const int* __restrict__ dst32) {
    __shared__ int nz;
    if (threadIdx.x == 0) nz = 0;
    __syncthreads();
    for (int i = threadIdx.x; i < 1024; i += blockDim.x) {
        if (src32[2 * i + 1] != 0 || dst32[2 * i + 1] != 0) nz = 1;
    }
    __syncthreads();
    if (threadIdx.x == 0) d_is64 = (nz == 0) ? 1 : 0;
}

__device__ __forceinline__ int load_idx(const int* p, int e, int is64) {
    return is64 ? p[2 * e] : p[e];
}

// ---------------- CSR build ----------------
__global__ void zero_deg_kernel() {
    int i = blockIdx.x * blockDim.x + threadIdx.x;
    if (i < NN) d_deg[i] = 0;
}

__global__ void count_kernel(const int* __restrict__ dst) {
    int is64 = d_is64;
    int e = blockIdx.x * blockDim.x + threadIdx.x;
    if (e < NE) {
        int d = load_idx(dst, e, is64);
        atomicAdd(&d_deg[d], 1);
    }
}

// Single-block exclusive scan of d_deg -> d_off (+ copy to d_cur). 1024 threads.
__global__ void scan_kernel() {
    __shared__ int wsum[32];
    __shared__ int carry_s;
    int tid = threadIdx.x, lane = tid & 31, wid = tid >> 5;
    if (tid == 0) carry_s = 0;
    __syncthreads();
    for (int base = 0; base < NN; base += 1024) {
        int carry = carry_s;
        int i = base + tid;
        int v = (i < NN) ? d_deg[i] : 0;
        int x = v;
        #pragma unroll
        for (int o = 1; o < 32; o <<= 1) {
            int y = __shfl_up_sync(0xffffffffu, x, o);
            if (lane >= o) x += y;
        }
        if (lane == 31) wsum[wid] = x;
        __syncthreads();
        if (wid == 0) {
            int s = wsum[lane];
            #pragma unroll
            for (int o = 1; o < 32; o <<= 1) {
                int y = __shfl_up_sync(0xffffffffu, s, o);
                if (lane >= o) s += y;
            }
            wsum[lane] = s;
        }
        __syncthreads();
        int incl = x + (wid > 0 ? wsum[wid - 1] : 0) + carry;
        if (i < NN) { d_off[i] = incl - v; d_cur[i] = incl - v; }
        if (i == NN - 1) d_off[NN] = incl;
        __syncthreads();
        if (tid == 1023) carry_s = incl;
        __syncthreads();
    }
}

__global__ void scatter_kernel(const int* __restrict__ src,
                               const int* __restrict__ dst) {
    int is64 = d_is64;
    int e = blockIdx.x * blockDim.x + threadIdx.x;
    if (e < NE) {
        int s = load_idx(src, e, is64);
        int d = load_idx(dst, e, is64);
        int pos = atomicAdd(&d_cur[d], 1);
        d_esrc[pos] = s;
    }
}

// ---------------- atomic-free mean aggregation: one warp per node ----------
__global__ void aggregate_kernel(const float4* __restrict__ featv) {
    int gwarp = (blockIdx.x * blockDim.x + threadIdx.x) >> 5;
    int lane = threadIdx.x & 31;
    if (gwarp >= NN) return;
    int beg = d_off[gwarp], end = d_off[gwarp + 1];
    float4 a0 = make_float4(0.f, 0.f, 0.f, 0.f);
    float4 a1 = make_float4(0.f, 0.f, 0.f, 0.f);
    int j = beg;
    for (; j + 1 < end; j += 2) {
        int s0 = d_esrc[j];
        int s1 = d_esrc[j + 1];
        float4 v0 = featv[(size_t)s0 * 32 + lane];
        float4 v1 = featv[(size_t)s1 * 32 + lane];
        a0.x += v0.x; a0.y += v0.y; a0.z += v0.z; a0.w += v0.w;
        a1.x += v1.x; a1.y += v1.y; a1.z += v1.z; a1.w += v1.w;
    }
    if (j < end) {
        int s0 = d_esrc[j];
        float4 v0 = featv[(size_t)s0 * 32 + lane];
        a0.x += v0.x; a0.y += v0.y; a0.z += v0.z; a0.w += v0.w;
    }
    int deg = end - beg;
    float inv = (deg > 0) ? (1.0f / (float)deg) : 0.0f;
    float4 r;
    r.x = (a0.x + a1.x) * inv;
    r.y = (a0.y + a1.y) * inv;
    r.z = (a0.z + a1.z) * inv;
    r.w = (a0.w + a1.w) * inv;
    ((float4*)d_agg)[(size_t)gwarp * 32 + lane] = r;
}

// ---------------- fused GEMM: out = [feat|agg] @ [W_self;W_neigh]^T + b ----
// M=50000, N=128, K=256. Block tile 64x128, BK=32, 256 threads, 8x4 per thread.
#define BM 64
#define BN 128
#define BK 32
#define TM 8
#define TN 4

__global__ __launch_bounds__(256) void gemm_kernel(
    const float* __restrict__ feat,
    const float* __restrict__ Wself,
    const float* __restrict__ bself,
    const float* __restrict__ Wneigh,
    const float* __restrict__ bias,
    float* __restrict__ out) {
    __shared__ float Xs[BK][BM + 4];   // transposed: [k][row]
    __shared__ float Ws[BK][BN + 4];   // transposed: [k][col]

    int tid = threadIdx.x;
    int m0 = blockIdx.x * BM;
    int cg = tid & 31;    // col group: cols [cg*4, cg*4+4)
    int rg = tid >> 5;    // row group: rows [rg*8, rg*8+8)

    float acc[TM][TN];
    #pragma unroll
    for (int i = 0; i < TM; ++i)
        #pragma unroll
        for (int jj = 0; jj < TN; ++jj) acc[i][jj] = 0.f;

    #pragma unroll 1
    for (int t = 0; t < 8; ++t) {
        int kbase = t * BK;
        const float* srcX = (kbase < 128) ? feat : d_agg;
        const float* srcW = (kbase < 128) ? Wself : Wneigh;
        int koff = kbase & 127;

        // load X tile: 64 rows x 32 k = 512 float4 (2 per thread)
        #pragma unroll
        for (int i = tid; i < 512; i += 256) {
            int r = i >> 3, kq = i & 7;
            int row = m0 + r;
            float4 v = make_float4(0.f, 0.f, 0.f, 0.f);
            if (row < NN)
                v = *(const float4*)(srcX + (size_t)row * 128 + koff + kq * 4);
            Xs[kq * 4 + 0][r] = v.x;
            Xs[kq * 4 + 1][r] = v.y;
            Xs[kq * 4 + 2][r] = v.z;
            Xs[kq * 4 + 3][r] = v.w;
        }
        // load W tile: 128 cols x 32 k = 1024 float4 (4 per thread)
        #pragma unroll
        for (int i = tid; i < 1024; i += 256) {
            int o = i >> 3, kq = i & 7;
            float4 v = *(const float4*)(srcW + (size_t)o * 128 + koff + kq * 4);
            Ws[kq * 4 + 0][o] = v.x;
            Ws[kq * 4 + 1][o] = v.y;
            Ws[kq * 4 + 2][o] = v.z;
            Ws[kq * 4 + 3][o] = v.w;
        }
        __syncthreads();

        #pragma unroll
        for (int kk = 0; kk < BK; ++kk) {
            float4 x0 = *(const float4*)&Xs[kk][rg * TM];
            float4 x1 = *(const float4*)&Xs[kk][rg * TM + 4];
            float4 w0 = *(const float4*)&Ws[kk][cg * TN];
            float xv[TM] = {x0.x, x0.y, x0.z, x0.w, x1.x, x1.y, x1.z, x1.w};
            float wv[TN] = {w0.x, w0.y, w0.z, w0.w};
            #pragma unroll
            for (int i = 0; i < TM; ++i)
                #pragma unroll
                for (int jj = 0; jj < TN; ++jj)
                    acc[i][jj] += xv[i] * wv[jj];
        }
        __syncthreads();
    }

    // epilogue: + b_self + bias, store float4
    float bb[TN];
    #pragma unroll
    for (int jj = 0; jj < TN; ++jj) {
        int c = cg * TN + jj;
        bb[jj] = bself[c] + bias[c];
    }
    #pragma unroll
    for (int i = 0; i < TM; ++i) {
        int row = m0 + rg * TM + i;
        if (row < NN) {
            float4 o4 = make_float4(acc[i][0] + bb[0], acc[i][1] + bb[1],
                                    acc[i][2] + bb[2], acc[i][3] + bb[3]);
            *(float4*)(out + (size_t)row * 128 + cg * TN) = o4;
        }
    }
}

// ---------------- launch ----------------
extern "C" void kernel_launch(void* const* d_in, const int* in_sizes, int n_in,
                              void* d_out, int out_size) {
    const float* feat   = (const float*)d_in[0];
    const int*   src    = (const int*)d_in[1];
    const int*   dst    = (const int*)d_in[2];
    const float* Wself  = (const float*)d_in[3];
    const float* bself  = (const float*)d_in[4];
    const float* Wneigh = (const float*)d_in[5];
    const float* bias   = (const float*)d_in[6];
    float* out = (float*)d_out;

    detect_kernel<<<1, 256>>>(src, dst);
    zero_deg_kernel<<<(NN + 255) / 256, 256>>>();
    count_kernel<<<(NE + 255) / 256, 256>>>(dst);
    scan_kernel<<<1, 1024>>>();
    scatter_kernel<<<(NE + 255) / 256, 256>>>(src, dst);
    aggregate_kernel<<<(NN * 32 + 255) / 256, 256>>>((const float4*)feat);
    gemm_kernel<<<(NN + BM - 1) / BM, 256>>>(feat, Wself, bself, Wneigh, bias, out);
}

// round 13
// speedup vs baseline: 1.0047x; 1.0047x over previous
#include <cuda_runtime.h>

#define NN 50000
#define NE 800000
#define D 128

// ---------------- device scratch (no allocations allowed) ----------------
__device__ int   d_is64;
__device__ int   d_deg[NN];
__device__ int   d_off[NN + 1];
__device__ int   d_cur[NN];
__device__ int   d_esrc[NE];
__device__ float d_agg[(size_t)NN * D];   // 25.6 MB mean-aggregated features

// ---------------- dtype detection: int64 vs int32 indices ----------------
// If indices are int64 (little-endian, values in [0,50000)), every odd 32-bit
// word is 0. If int32, odd words are random dst/src indices (P(all zero)≈0).
__global__ void detect_kernel(const int* __restrict__ src32,
                              const int* __restrict__ dst32) {
    __shared__ int nz;
    if (threadIdx.x == 0) nz = 0;
    __syncthreads();
    for (int i = threadIdx.x; i < 1024; i += blockDim.x) {
        if (src32[2 * i + 1] != 0 || dst32[2 * i + 1] != 0) nz = 1;
    }
    __syncthreads();
    if (threadIdx.x == 0) d_is64 = (nz == 0) ? 1 : 0;
}

__device__ __forceinline__ int load_idx(const int* p, int e, int is64) {
    return is64 ? p[2 * e] : p[e];
}

// ---------------- CSR build ----------------
__global__ void zero_deg_kernel() {
    int i = blockIdx.x * blockDim.x + threadIdx.x;
    if (i < NN) d_deg[i] = 0;
}

__global__ void count_kernel(const int* __restrict__ dst) {
    int is64 = d_is64;
    int e = blockIdx.x * blockDim.x + threadIdx.x;
    if (e < NE) {
        int d = load_idx(dst, e, is64);
        atomicAdd(&d_deg[d], 1);
    }
}

// Single-block exclusive scan of d_deg -> d_off (+ copy to d_cur). 1024 threads.
__global__ void scan_kernel() {
    __shared__ int wsum[32];
    __shared__ int carry_s;
    int tid = threadIdx.x, lane = tid & 31, wid = tid >> 5;
    if (tid == 0) carry_s = 0;
    __syncthreads();
    for (int base = 0; base < NN; base += 1024) {
        int carry = carry_s;
        int i = base + tid;
        int v = (i < NN) ? d_deg[i] : 0;
        int x = v;
        #pragma unroll
        for (int o = 1; o < 32; o <<= 1) {
            int y = __shfl_up_sync(0xffffffffu, x, o);
            if (lane >= o) x += y;
        }
        if (lane == 31) wsum[wid] = x;
        __syncthreads();
        if (wid == 0) {
            int s = wsum[lane];
            #pragma unroll
            for (int o = 1; o < 32; o <<= 1) {
                int y = __shfl_up_sync(0xffffffffu, s, o);
                if (lane >= o) s += y;
            }
            wsum[lane] = s;
        }
        __syncthreads();
        int incl = x + (wid > 0 ? wsum[wid - 1] : 0) + carry;
        if (i < NN) { d_off[i] = incl - v; d_cur[i] = incl - v; }
        if (i == NN - 1) d_off[NN] = incl;
        __syncthreads();
        if (tid == 1023) carry_s = incl;
        __syncthreads();
    }
}

__global__ void scatter_kernel(const int* __restrict__ src,
                               const int* __restrict__ dst) {
    int is64 = d_is64;
    int e = blockIdx.x * blockDim.x + threadIdx.x;
    if (e < NE) {
        int s = load_idx(src, e, is64);
        int d = load_idx(dst, e, is64);
        int pos = atomicAdd(&d_cur[d], 1);
        d_esrc[pos] = s;
    }
}

// ---------------- atomic-free mean aggregation: one warp per node ----------
__global__ void aggregate_kernel(const float4* __restrict__ featv) {
    int gwarp = (blockIdx.x * blockDim.x + threadIdx.x) >> 5;
    int lane = threadIdx.x & 31;
    if (gwarp >= NN) return;
    int beg = d_off[gwarp], end = d_off[gwarp + 1];
    float4 a0 = make_float4(0.f, 0.f, 0.f, 0.f);
    float4 a1 = make_float4(0.f, 0.f, 0.f, 0.f);
    int j = beg;
    for (; j + 1 < end; j += 2) {
        int s0 = d_esrc[j];
        int s1 = d_esrc[j + 1];
        float4 v0 = featv[(size_t)s0 * 32 + lane];
        float4 v1 = featv[(size_t)s1 * 32 + lane];
        a0.x += v0.x; a0.y += v0.y; a0.z += v0.z; a0.w += v0.w;
        a1.x += v1.x; a1.y += v1.y; a1.z += v1.z; a1.w += v1.w;
    }
    if (j < end) {
        int s0 = d_esrc[j];
        float4 v0 = featv[(size_t)s0 * 32 + lane];
        a0.x += v0.x; a0.y += v0.y; a0.z += v0.z; a0.w += v0.w;
    }
    int deg = end - beg;
    float inv = (deg > 0) ? (1.0f / (float)deg) : 0.0f;
    float4 r;
    r.x = (a0.x + a1.x) * inv;
    r.y = (a0.y + a1.y) * inv;
    r.z = (a0.z + a1.z) * inv;
    r.w = (a0.w + a1.w) * inv;
    ((float4*)d_agg)[(size_t)gwarp * 32 + lane] = r;
}

// ---------------- fused GEMM: out = [feat|agg] @ [W_self;W_neigh]^T + b ----
// M=50000, N=128, K=256. Block tile 64x128, BK=32, 256 threads, 8x4 per thread.
#define BM 64
#define BN 128
#define BK 32
#define TM 8
#define TN 4

__global__ __launch_bounds__(256) void gemm_kernel(
    const float* __restrict__ feat,
    const float* __restrict__ Wself,
    const float* __restrict__ bself,
    const float* __restrict__ Wneigh,
    const float* __restrict__ bias,
    float* __restrict__ out) {
    __shared__ float Xs[BK][BM + 4];   // transposed: [k][row]
    __shared__ float Ws[BK][BN + 4];   // transposed: [k][col]

    int tid = threadIdx.x;
    int m0 = blockIdx.x * BM;
    int cg = tid & 31;    // col group: cols [cg*4, cg*4+4)
    int rg = tid >> 5;    // row group: rows [rg*8, rg*8+8)

    float acc[TM][TN];
    #pragma unroll
    for (int i = 0; i < TM; ++i)
        #pragma unroll
        for (int jj = 0; jj < TN; ++jj) acc[i][jj] = 0.f;

    #pragma unroll 1
    for (int t = 0; t < 8; ++t) {
        int kbase = t * BK;
        const float* srcX = (kbase < 128) ? feat : d_agg;
        const float* srcW = (kbase < 128) ? Wself : Wneigh;
        int koff = kbase & 127;

        // load X tile: 64 rows x 32 k = 512 float4 (2 per thread)
        #pragma unroll
        for (int i = tid; i < 512; i += 256) {
            int r = i >> 3, kq = i & 7;
            int row = m0 + r;
            float4 v = make_float4(0.f, 0.f, 0.f, 0.f);
            if (row < NN)
                v = *(const float4*)(srcX + (size_t)row * 128 + koff + kq * 4);
            Xs[kq * 4 + 0][r] = v.x;
            Xs[kq * 4 + 1][r] = v.y;
            Xs[kq * 4 + 2][r] = v.z;
            Xs[kq * 4 + 3][r] = v.w;
        }
        // load W tile: 128 cols x 32 k = 1024 float4 (4 per thread)
        #pragma unroll
        for (int i = tid; i < 1024; i += 256) {
            int o = i >> 3, kq = i & 7;
            float4 v = *(const float4*)(srcW + (size_t)o * 128 + koff + kq * 4);
            Ws[kq * 4 + 0][o] = v.x;
            Ws[kq * 4 + 1][o] = v.y;
            Ws[kq * 4 + 2][o] = v.z;
            Ws[kq * 4 + 3][o] = v.w;
        }
        __syncthreads();

        #pragma unroll
        for (int kk = 0; kk < BK; ++kk) {
            float4 x0 = *(const float4*)&Xs[kk][rg * TM];
            float4 x1 = *(const float4*)&Xs[kk][rg * TM + 4];
            float4 w0 = *(const float4*)&Ws[kk][cg * TN];
            float xv[TM] = {x0.x, x0.y, x0.z, x0.w, x1.x, x1.y, x1.z, x1.w};
            float wv[TN] = {w0.x, w0.y, w0.z, w0.w};
            #pragma unroll
            for (int i = 0; i < TM; ++i)
                #pragma unroll
                for (int jj = 0; jj < TN; ++jj)
                    acc[i][jj] += xv[i] * wv[jj];
        }
        __syncthreads();
    }

    // epilogue: + b_self + bias, store float4
    float bb[TN];
    #pragma unroll
    for (int jj = 0; jj < TN; ++jj) {
        int c = cg * TN + jj;
        bb[jj] = bself[c] + bias[c];
    }
    #pragma unroll
    for (int i = 0; i < TM; ++i) {
        int row = m0 + rg * TM + i;
        if (row < NN) {
            float4 o4 = make_float4(acc[i][0] + bb[0], acc[i][1] + bb[1],
                                    acc[i][2] + bb[2], acc[i][3] + bb[3]);
            *(float4*)(out + (size_t)row * 128 + cg * TN) = o4;
        }
    }
}

// ---------------- launch ----------------
extern "C" void kernel_launch(void* const* d_in, const int* in_sizes, int n_in,
                              void* d_out, int out_size) {
    const float* feat   = (const float*)d_in[0];
    const int*   src    = (const int*)d_in[1];
    const int*   dst    = (const int*)d_in[2];
    const float* Wself  = (const float*)d_in[3];
    const float* bself  = (const float*)d_in[4];
    const float* Wneigh = (const float*)d_in[5];
    const float* bias   = (const float*)d_in[6];
    float* out = (float*)d_out;

    detect_kernel<<<1, 256>>>(src, dst);
    zero_deg_kernel<<<(NN + 255) / 256, 256>>>();
    count_kernel<<<(NE + 255) / 256, 256>>>(dst);
    scan_kernel<<<1, 1024>>>();
    scatter_kernel<<<(NE + 255) / 256, 256>>>(src, dst);
    aggregate_kernel<<<(NN * 32 + 255) / 256, 256>>>((const float4*)feat);
    gemm_kernel<<<(NN + BM - 1) / BM, 256>>>(feat, Wself, bself, Wneigh, bias, out);
}